// round 16
// baseline (speedup 1.0000x reference)
#include <cuda_runtime.h>
#include <math.h>

#define BB 64
#define NN 16800
#define CC 21
#define TPB 256
#define NBLK 66          // ceil(16800/256)
#define FP32_EPS 1.1920928955078125e-07f
#define FBINS 512        // linear bins, width 1/32 over [0,16)

// ---------------- scratch (device globals; no allocation) ----------------
__device__ float    d_psl1[BB * NBLK];
__device__ float    d_pce [BB * NBLK];
__device__ int      d_ppos[BB * NBLK];
__device__ unsigned d_gcnt[BB * FBINS];   // zero-init; k_fin re-zeros (replay-invariant)
__device__ float    d_gsum[BB * FBINS];   // zero-init; k_fin re-zeros
__device__ float    d_res [BB * 3];
__device__ int      d_done;               // ticket (self-resetting)

__device__ __forceinline__ float smooth_l1(float d) {
    float a = fabsf(d);
    return (a < 1.f) ? (0.5f * a * a) : (a - 0.5f);
}

// linear equal-width bin over [0,16), width 1/32
__device__ __forceinline__ unsigned fbin(float v) {
    return min((unsigned)(FBINS - 1), (unsigned)(v * 32.0f));
}

// ---------------- main: sl1 + ce + partials + fused 512-bin histogram ----------------
// 2-barrier structure: hist has dedicated SMEM, zeroed during staging.
__global__ void __launch_bounds__(TPB, 8)
k_main(const float4* __restrict__ pb,
       const float4* __restrict__ gb,
       const float4* __restrict__ pl4,
       const int*    __restrict__ gl,
       const float4* __restrict__ anc)
{
    __shared__ __align__(16) float s_lab[TPB * CC];   // 21504 B
    __shared__ unsigned hc[FBINS];                    // 2048 B
    __shared__ float    hf[FBINS];                    // 2048 B
    __shared__ float rs[8], rc[8];
    __shared__ int   rp[8];

    const int b    = blockIdx.y;
    const int base = blockIdx.x * TPB;
    const int tid  = threadIdx.x;
    const int lane = tid & 31;
    const int w    = tid >> 5;
    const int n    = base + tid;
    const int cnt  = min(TPB, NN - base);

    // phase 1: zero hist + stage p_labels (evict-first streaming loads)
    #pragma unroll
    for (int i = tid; i < FBINS; i += TPB) { hc[i] = 0u; hf[i] = 0.f; }
    {
        const float4* src = pl4 + ((size_t)b * NN + base) * CC / 4;
        float4* dst = (float4*)s_lab;
        const int tot4 = (cnt * CC) >> 2;
        for (int i = tid; i < tot4; i += TPB) dst[i] = __ldcs(&src[i]);
    }
    __syncthreads();   // SYNC1: staging + hist-zero complete

    // phase 2: compute + hist atomics + partials warp-reduce
    float sl1 = 0.f, ce = 0.f;
    int pos = 0;
    if (tid < cnt) {
        float4 a = anc[n];
        float4 g = __ldcs(&gb[b * NN + n]);
        float4 p = __ldcs(&pb[b * NN + n]);
        float t0 = 10.f * (g.x - a.x) / a.z;
        float t1 = 10.f * (g.y - a.y) / a.w;
        float t2 = 5.f * __logf(g.z / a.z);
        float t3 = 5.f * __logf(g.w / a.w);
        sl1 = smooth_l1(p.x - t0) + smooth_l1(p.y - t1)
            + smooth_l1(p.z - t2) + smooth_l1(p.w - t3);

        const float* x = s_lab + tid * CC;   // stride 21, conflict-free
        float s = 0.f;
        #pragma unroll
        for (int j = 0; j < CC; j++) s += __expf(x[j]);
        int lab = gl[b * NN + n];
        ce = __logf(s) - x[lab];
        pos = (lab > 0);

        const float negv = pos ? 0.f : fmaxf(ce, 0.f);
        const unsigned bin = fbin(negv);
        atomicAdd(&hc[bin], 1u);
        atomicAdd(&hf[bin], negv);
    }
    {
        float vsl = pos ? sl1 : 0.f;
        float vce = pos ? ce  : 0.f;
        #pragma unroll
        for (int o = 16; o; o >>= 1) {
            vsl += __shfl_down_sync(0xFFFFFFFFu, vsl, o);
            vce += __shfl_down_sync(0xFFFFFFFFu, vce, o);
        }
        int wp = __popc(__ballot_sync(0xFFFFFFFFu, pos));
        if (lane == 0) { rs[w] = vsl; rc[w] = vce; rp[w] = wp; }
    }
    __syncthreads();   // SYNC2: hist atomics + partials complete

    // phase 3: partial store (tid0) + hist merge (all threads), no more barriers
    if (tid == 0) {
        float A = 0.f, Cc = 0.f; int P = 0;
        #pragma unroll
        for (int i = 0; i < 8; i++) { A += rs[i]; Cc += rc[i]; P += rp[i]; }
        const int idx = b * NBLK + blockIdx.x;
        d_psl1[idx] = A;
        d_pce [idx] = Cc;
        d_ppos[idx] = P;
    }
    #pragma unroll
    for (int i = tid; i < FBINS; i += TPB) {
        unsigned c = hc[i];
        if (c) {
            atomicAdd(&d_gcnt[b * FBINS + i], c);
            atomicAdd(&d_gsum[b * FBINS + i], hf[i]);
        }
    }
}

// ---------------- fin: one block per batch (R13-proven) + PDL early start ----------------
__global__ void __launch_bounds__(TPB)
k_fin(float* __restrict__ out)
{
    const int b    = blockIdx.x;
    const int tid  = threadIdx.x;
    const int lane = tid & 31;
    const int w    = tid >> 5;

#if __CUDA_ARCH__ >= 900
    cudaGridDependencySynchronize();
#endif

    __shared__ float a66[NBLK], c66[NBLK];
    __shared__ int   p66[NBLK];
    __shared__ unsigned s_wc[8];
    __shared__ float    s_wf[8];
    __shared__ float red[8];
    __shared__ float sA, sC, s_negsum;
    __shared__ int   sP, s_lastg;

    // thread owns 2 consecutive bins; load (L2/DRAM) + zero for replay
    unsigned c2[2]; float f2[2];
    {
        const int gbase = b * FBINS + tid * 2;
        #pragma unroll
        for (int j = 0; j < 2; j++) {
            c2[j] = d_gcnt[gbase + j];
            f2[j] = d_gsum[gbase + j];
            d_gcnt[gbase + j] = 0u;
            d_gsum[gbase + j] = 0.f;
        }
    }
    if (tid < NBLK) {
        const int idx = b * NBLK + tid;
        a66[tid] = d_psl1[idx];
        c66[tid] = d_pce [idx];
        p66[tid] = d_ppos[idx];
    }
    if (tid == 0) s_negsum = 0.f;
    __syncthreads();

    // reduce partials (warp 0)
    if (tid < 32) {
        float A  = a66[tid] + a66[tid + 32] + ((tid < 2) ? a66[tid + 64] : 0.f);
        float Cc = c66[tid] + c66[tid + 32] + ((tid < 2) ? c66[tid + 64] : 0.f);
        int   P  = p66[tid] + p66[tid + 32] + ((tid < 2) ? p66[tid + 64] : 0);
        #pragma unroll
        for (int o = 16; o; o >>= 1) {
            A  += __shfl_down_sync(0xFFFFFFFFu, A, o);
            Cc += __shfl_down_sync(0xFFFFFFFFu, Cc, o);
            P  += __shfl_down_sync(0xFFFFFFFFu, P, o);
        }
        if (tid == 0) { sA = A; sC = Cc; sP = P; }
    }

    // per-warp inclusive suffix over lanes (higher lane = higher bins)
    const unsigned ct = c2[0] + c2[1];
    const float    ft = f2[0] + f2[1];
    unsigned sc_ = ct; float sf_ = ft;
    #pragma unroll
    for (int o = 1; o < 32; o <<= 1) {
        unsigned vc = __shfl_down_sync(0xFFFFFFFFu, sc_, o);
        float    vf = __shfl_down_sync(0xFFFFFFFFu, sf_, o);
        if (lane + o < 32) { sc_ += vc; sf_ += vf; }
    }
    if (lane == 0) { s_wc[w] = sc_; s_wf[w] = sf_; }
    __syncthreads();

    const int posn = sP;
    const int k0   = min(3 * posn, NN);

    if (k0 > 0) {
        unsigned awc = 0; float awf = 0.f;
        #pragma unroll
        for (int j = 0; j < 8; j++) if (j > w) { awc += s_wc[j]; awf += s_wf[j]; }
        const unsigned above_c = awc + (sc_ - ct);
        const float    above_f = awf + (sf_ - ft);

        if (above_c < (unsigned)k0 && above_c + ct >= (unsigned)k0) {
            unsigned cum = above_c; float fa = above_f;
            #pragma unroll
            for (int j = 1; j >= 0; j--) {
                unsigned h = c2[j];
                if (cum + h >= (unsigned)k0) {
                    const float mean = f2[j] / (float)h;
                    s_negsum = fa + (float)(k0 - (int)cum) * mean;
                    break;
                }
                cum += h; fa += f2[j];
            }
        }
    }
    __syncthreads();

    if (tid == 0) {
        float lb = sA;
        float ll = sC + s_negsum;
        float nm = (posn > 0) ? 1.f : 0.f;
        float pf = fmaxf((float)posn, FP32_EPS);
        d_res[b * 3 + 0] = (lb + ll) * nm / pf;
        d_res[b * 3 + 1] = lb * nm / pf;
        d_res[b * 3 + 2] = ll * nm / pf;
        __threadfence();
        s_lastg = (atomicAdd(&d_done, 1) == BB - 1);
    }
    __syncthreads();

    if (s_lastg) {
        __threadfence();
        float lt = 0.f, vb = 0.f, vl = 0.f;
        if (tid < BB) {
            volatile float* r = d_res;
            lt = r[tid * 3 + 0];
            vb = r[tid * 3 + 1];
            vl = r[tid * 3 + 2];
        }
        if (tid < 64) {
            #pragma unroll
            for (int o = 16; o; o >>= 1) {
                lt += __shfl_down_sync(0xFFFFFFFFu, lt, o);
                vb += __shfl_down_sync(0xFFFFFFFFu, vb, o);
                vl += __shfl_down_sync(0xFFFFFFFFu, vl, o);
            }
            if ((tid & 31) == 0) {
                red[tid >> 5]       = lt;
                red[(tid >> 5) + 2] = vb;
                red[(tid >> 5) + 4] = vl;
            }
        }
        __syncthreads();
        if (tid == 0) {
            out[0] = (red[0] + red[1]) * (1.f / 64.f);
            out[1] = (red[2] + red[3]) * (1.f / 64.f);
            out[2] = (red[4] + red[5]) * (1.f / 64.f);
            d_done = 0;   // self-reset for next graph replay
        }
    }
}

// ---------------- launch ----------------
extern "C" void kernel_launch(void* const* d_in, const int* in_sizes, int n_in,
                              void* d_out, int out_size) {
    const float4* pb  = (const float4*)d_in[0];
    const float4* gb  = (const float4*)d_in[1];
    const float4* pl4 = (const float4*)d_in[2];
    const int*    gl  = (const int*)d_in[3];
    const float4* anc = (const float4*)d_in[4];
    float* out = (float*)d_out;

    dim3 gBN(NBLK, BB);
    k_main<<<gBN, TPB>>>(pb, gb, pl4, gl, anc);

    cudaLaunchConfig_t cfg = {};
    cfg.gridDim  = dim3(BB, 1, 1);
    cfg.blockDim = dim3(TPB, 1, 1);
    cudaLaunchAttribute attr[1];
    attr[0].id = cudaLaunchAttributeProgrammaticStreamSerialization;
    attr[0].val.programmaticStreamSerializationAllowed = 1;
    cfg.attrs = attr;
    cfg.numAttrs = 1;
    cudaLaunchKernelEx(&cfg, k_fin, out);
}

// round 17
// speedup vs baseline: 1.0726x; 1.0726x over previous
#include <cuda_runtime.h>
#include <math.h>

#define BB 64
#define NN 16800
#define CC 21
#define TPB 512                  // k_main block size
#define NBLK 33                  // ceil(16800/512)
#define TPF 256                  // k_fin block size
#define FP32_EPS 1.1920928955078125e-07f
#define FBINS 512                // linear bins, width 1/32 over [0,16)

// ---------------- scratch (device globals; no allocation) ----------------
__device__ float    d_psl1[BB * NBLK];
__device__ float    d_pce [BB * NBLK];
__device__ int      d_ppos[BB * NBLK];
// interleaved per-batch histogram: [cnt(bin), sum(bin)] pairs; zero-init, k_fin re-zeros
__device__ __align__(16) unsigned d_ghist[BB * FBINS * 2];
__device__ float    d_res [BB * 3];
__device__ int      d_done;      // ticket (self-resetting)

__device__ __forceinline__ float smooth_l1(float d) {
    float a = fabsf(d);
    return (a < 1.f) ? (0.5f * a * a) : (a - 0.5f);
}

// linear equal-width bin over [0,16), width 1/32
__device__ __forceinline__ unsigned fbin(float v) {
    return min((unsigned)(FBINS - 1), (unsigned)(v * 32.0f));
}

// gpu-scope acq_rel fetch-add (orders prior stores / subsequent loads, no MEMBAR.GL)
__device__ __forceinline__ int atom_add_acqrel(int* p, int v) {
    int old;
    asm volatile("atom.global.acq_rel.gpu.add.s32 %0, [%1], %2;"
                 : "=r"(old) : "l"(p), "r"(v) : "memory");
    return old;
}

// ---------------- main: sl1 + ce + partials + fused interleaved histogram ----------------
__global__ void __launch_bounds__(TPB, 4)
k_main(const float4* __restrict__ pb,
       const float4* __restrict__ gb,
       const float4* __restrict__ pl4,
       const int*    __restrict__ gl,
       const float4* __restrict__ anc)
{
    __shared__ __align__(16) float s_lab[TPB * CC];   // 43008 B
    __shared__ unsigned s_hist[FBINS * 2];            // 4096 B, [cnt,sum] interleaved
    __shared__ float rs[16], rc[16];
    __shared__ int   rp[16];

    const int b    = blockIdx.y;
    const int base = blockIdx.x * TPB;
    const int tid  = threadIdx.x;
    const int lane = tid & 31;
    const int w    = tid >> 5;
    const int n    = base + tid;
    const int cnt  = min(TPB, NN - base);

    // phase 1: zero hist + stage p_labels (evict-first streaming loads)
    #pragma unroll
    for (int i = tid; i < FBINS * 2; i += TPB) s_hist[i] = 0u;
    {
        const float4* src = pl4 + ((size_t)b * NN + base) * CC / 4;
        float4* dst = (float4*)s_lab;
        const int tot4 = (cnt * CC) >> 2;
        for (int i = tid; i < tot4; i += TPB) dst[i] = __ldcs(&src[i]);
    }
    __syncthreads();   // SYNC1

    // phase 2: compute + hist atomics + partials warp-reduce
    float sl1 = 0.f, ce = 0.f;
    int pos = 0;
    if (tid < cnt) {
        float4 a = anc[n];
        float4 g = __ldcs(&gb[b * NN + n]);
        float4 p = __ldcs(&pb[b * NN + n]);
        float t0 = 10.f * (g.x - a.x) / a.z;
        float t1 = 10.f * (g.y - a.y) / a.w;
        float t2 = 5.f * __logf(g.z / a.z);
        float t3 = 5.f * __logf(g.w / a.w);
        sl1 = smooth_l1(p.x - t0) + smooth_l1(p.y - t1)
            + smooth_l1(p.z - t2) + smooth_l1(p.w - t3);

        const float* x = s_lab + tid * CC;   // stride 21, conflict-free
        float s = 0.f;
        #pragma unroll
        for (int j = 0; j < CC; j++) s += __expf(x[j]);
        int lab = gl[b * NN + n];
        ce = __logf(s) - x[lab];
        pos = (lab > 0);

        const float negv = pos ? 0.f : fmaxf(ce, 0.f);
        const unsigned bin = fbin(negv);
        atomicAdd(&s_hist[2 * bin], 1u);
        atomicAdd((float*)&s_hist[2 * bin + 1], negv);
    }
    {
        float vsl = pos ? sl1 : 0.f;
        float vce = pos ? ce  : 0.f;
        #pragma unroll
        for (int o = 16; o; o >>= 1) {
            vsl += __shfl_down_sync(0xFFFFFFFFu, vsl, o);
            vce += __shfl_down_sync(0xFFFFFFFFu, vce, o);
        }
        int wp = __popc(__ballot_sync(0xFFFFFFFFu, pos));
        if (lane == 0) { rs[w] = vsl; rc[w] = vce; rp[w] = wp; }
    }
    __syncthreads();   // SYNC2

    // phase 3: partial store + interleaved hist merge (adjacent words, 1 line/bin)
    if (tid == 0) {
        float A = 0.f, Cc = 0.f; int P = 0;
        #pragma unroll
        for (int i = 0; i < 16; i++) { A += rs[i]; Cc += rc[i]; P += rp[i]; }
        const int idx = b * NBLK + blockIdx.x;
        d_psl1[idx] = A;
        d_pce [idx] = Cc;
        d_ppos[idx] = P;
    }
    #pragma unroll
    for (int i = tid; i < FBINS; i += TPB) {      // one bin per thread
        unsigned c = s_hist[2 * i];
        if (c) {
            unsigned* gp = &d_ghist[b * FBINS * 2 + 2 * i];
            atomicAdd(gp, c);
            atomicAdd((float*)(gp + 1), __uint_as_float(s_hist[2 * i + 1]));
        }
    }
}

// ---------------- fin: one block per batch; uint4 hist access; acq_rel ticket ----------------
__global__ void __launch_bounds__(TPF)
k_fin(float* __restrict__ out)
{
    const int b    = blockIdx.x;
    const int tid  = threadIdx.x;
    const int lane = tid & 31;
    const int w    = tid >> 5;

#if __CUDA_ARCH__ >= 900
    cudaGridDependencySynchronize();
#endif

    __shared__ float a33[64], c33[64];
    __shared__ int   p33[64];
    __shared__ unsigned s_wc[8];
    __shared__ float    s_wf[8];
    __shared__ float red[8];
    __shared__ float sA, sC, s_negsum;
    __shared__ int   sP, s_lastg;

    // thread owns 2 consecutive bins: ONE uint4 load + ONE uint4 zero-store
    unsigned c2[2]; float f2[2];
    {
        uint4* gp = (uint4*)&d_ghist[b * FBINS * 2 + tid * 4];
        uint4 v = *gp;
        *gp = make_uint4(0u, 0u, 0u, 0u);
        c2[0] = v.x; f2[0] = __uint_as_float(v.y);
        c2[1] = v.z; f2[1] = __uint_as_float(v.w);
    }
    if (tid < 64) {   // pad partials to 64 (NBLK=33)
        a33[tid] = (tid < NBLK) ? d_psl1[b * NBLK + tid] : 0.f;
        c33[tid] = (tid < NBLK) ? d_pce [b * NBLK + tid] : 0.f;
        p33[tid] = (tid < NBLK) ? d_ppos[b * NBLK + tid] : 0;
    }
    if (tid == 0) s_negsum = 0.f;
    __syncthreads();

    // reduce partials (warp 0)
    if (tid < 32) {
        float A  = a33[tid] + a33[tid + 32];
        float Cc = c33[tid] + c33[tid + 32];
        int   P  = p33[tid] + p33[tid + 32];
        #pragma unroll
        for (int o = 16; o; o >>= 1) {
            A  += __shfl_down_sync(0xFFFFFFFFu, A, o);
            Cc += __shfl_down_sync(0xFFFFFFFFu, Cc, o);
            P  += __shfl_down_sync(0xFFFFFFFFu, P, o);
        }
        if (tid == 0) { sA = A; sC = Cc; sP = P; }
    }

    // per-warp inclusive suffix over lanes (higher lane = higher bins)
    const unsigned ct = c2[0] + c2[1];
    const float    ft = f2[0] + f2[1];
    unsigned sc_ = ct; float sf_ = ft;
    #pragma unroll
    for (int o = 1; o < 32; o <<= 1) {
        unsigned vc = __shfl_down_sync(0xFFFFFFFFu, sc_, o);
        float    vf = __shfl_down_sync(0xFFFFFFFFu, sf_, o);
        if (lane + o < 32) { sc_ += vc; sf_ += vf; }
    }
    if (lane == 0) { s_wc[w] = sc_; s_wf[w] = sf_; }
    __syncthreads();

    const int posn = sP;
    const int k0   = min(3 * posn, NN);

    if (k0 > 0) {
        unsigned awc = 0; float awf = 0.f;
        #pragma unroll
        for (int j = 0; j < 8; j++) if (j > w) { awc += s_wc[j]; awf += s_wf[j]; }
        const unsigned above_c = awc + (sc_ - ct);
        const float    above_f = awf + (sf_ - ft);

        if (above_c < (unsigned)k0 && above_c + ct >= (unsigned)k0) {
            unsigned cum = above_c; float fa = above_f;
            #pragma unroll
            for (int j = 1; j >= 0; j--) {
                unsigned h = c2[j];
                if (cum + h >= (unsigned)k0) {
                    const float mean = f2[j] / (float)h;
                    s_negsum = fa + (float)(k0 - (int)cum) * mean;
                    break;
                }
                cum += h; fa += f2[j];
            }
        }
    }
    __syncthreads();

    if (tid == 0) {
        float lb = sA;
        float ll = sC + s_negsum;
        float nm = (posn > 0) ? 1.f : 0.f;
        float pf = fmaxf((float)posn, FP32_EPS);
        d_res[b * 3 + 0] = (lb + ll) * nm / pf;
        d_res[b * 3 + 1] = lb * nm / pf;
        d_res[b * 3 + 2] = ll * nm / pf;
        // acq_rel ticket: releases d_res stores, acquires others' (no MEMBAR.GL)
        s_lastg = (atom_add_acqrel(&d_done, 1) == BB - 1);
    }
    __syncthreads();

    if (s_lastg) {
        float lt = 0.f, vb = 0.f, vl = 0.f;
        if (tid < BB) {
            volatile float* r = d_res;
            lt = r[tid * 3 + 0];
            vb = r[tid * 3 + 1];
            vl = r[tid * 3 + 2];
        }
        if (tid < 64) {
            #pragma unroll
            for (int o = 16; o; o >>= 1) {
                lt += __shfl_down_sync(0xFFFFFFFFu, lt, o);
                vb += __shfl_down_sync(0xFFFFFFFFu, vb, o);
                vl += __shfl_down_sync(0xFFFFFFFFu, vl, o);
            }
            if ((tid & 31) == 0) {
                red[tid >> 5]       = lt;
                red[(tid >> 5) + 2] = vb;
                red[(tid >> 5) + 4] = vl;
            }
        }
        __syncthreads();
        if (tid == 0) {
            out[0] = (red[0] + red[1]) * (1.f / 64.f);
            out[1] = (red[2] + red[3]) * (1.f / 64.f);
            out[2] = (red[4] + red[5]) * (1.f / 64.f);
            d_done = 0;   // self-reset for next graph replay
        }
    }
}

// ---------------- launch ----------------
extern "C" void kernel_launch(void* const* d_in, const int* in_sizes, int n_in,
                              void* d_out, int out_size) {
    const float4* pb  = (const float4*)d_in[0];
    const float4* gb  = (const float4*)d_in[1];
    const float4* pl4 = (const float4*)d_in[2];
    const int*    gl  = (const int*)d_in[3];
    const float4* anc = (const float4*)d_in[4];
    float* out = (float*)d_out;

    dim3 gBN(NBLK, BB);
    k_main<<<gBN, TPB>>>(pb, gb, pl4, gl, anc);

    cudaLaunchConfig_t cfg = {};
    cfg.gridDim  = dim3(BB, 1, 1);
    cfg.blockDim = dim3(TPF, 1, 1);
    cudaLaunchAttribute attr[1];
    attr[0].id = cudaLaunchAttributeProgrammaticStreamSerialization;
    attr[0].val.programmaticStreamSerializationAllowed = 1;
    cfg.attrs = attr;
    cfg.numAttrs = 1;
    cudaLaunchKernelEx(&cfg, k_fin, out);
}